// round 17
// baseline (speedup 1.0000x reference)
#include <cuda_runtime.h>
#include <cuda_fp16.h>
#include <cstdint>

// out = x @ V @ diag(S) @ U^T + bias  via mma.sync m16n8k16 fp16 (f32 accum).
// SINGLE launch. Grid = 512 prep + 512 GEMM1 + 2048 GEMM2 blocks.
// Prep block p: (a) 8 V-transpose tiles -> vdone, (b) x rows [16p,16p+16) f32->h
// -> xdone[p>>3], (c) 1/512 of U f32->h -> udone. Fat blocks, MLP-16 loads.
// GEMM1 tile gates on vdone==512 && xdone[m]==8; GEMM2 on udone==512 && mdone[m]==8.
// gemm_tile: R16 config (128 thr, 4 warps 64x64, 3-stage cp.async, 2 CTAs/SM).

#define CTA_M 128
#define CTA_N 128
#define CTA_K 64
#define NSTAGES 3

static constexpr int A_BYTES = CTA_M * CTA_K * 2;          // 16384
static constexpr int B_BYTES = CTA_N * CTA_K * 2;          // 16384
static constexpr int STAGE_BYTES = A_BYTES + B_BYTES;      // 32768
static constexpr int SMEM_TOTAL = NSTAGES * STAGE_BYTES;   // 98304

static constexpr int PREP_BLKS = 512;
static constexpr int G1_TILES = 512;    // 64 m x 8 n
static constexpr int G2_TILES = 2048;   // 64 m x 32 n
static constexpr int N_BLOCKS = PREP_BLKS + G1_TILES + G2_TILES;  // 3072

// Scratch (allocation-free rule: __device__ globals)
__device__ __align__(128) __half g_xh[8192 * 4096];
__device__ __align__(128) __half g_Vth[1024 * 4096];
__device__ __align__(128) __half g_Uh[4096 * 1024];
__device__ __align__(128) __half g_Ts[8192 * 1024];
__device__ unsigned g_vdone, g_udone;
__device__ unsigned g_xdone[64];
__device__ unsigned g_mdone[64];

__device__ __forceinline__ uint32_t smem_u32(const void* p) {
    uint32_t a;
    asm("{ .reg .u64 t; cvta.to.shared.u64 t, %1; cvt.u32.u64 %0, t; }" : "=r"(a) : "l"(p));
    return a;
}
__device__ __forceinline__ void cp16(uint32_t dst, const void* src) {
    asm volatile("cp.async.cg.shared.global [%0], [%1], 16;" :: "r"(dst), "l"(src));
}
__device__ __forceinline__ void cp_commit() {
    asm volatile("cp.async.commit_group;" ::: "memory");
}
template <int N>
__device__ __forceinline__ void cp_wait() {
    asm volatile("cp.async.wait_group %0;" :: "n"(N) : "memory");
}
__device__ __forceinline__ void ldsm4(uint32_t* r, uint32_t addr) {
    asm volatile("ldmatrix.sync.aligned.m8n8.x4.shared.b16 {%0,%1,%2,%3}, [%4];"
                 : "=r"(r[0]), "=r"(r[1]), "=r"(r[2]), "=r"(r[3]) : "r"(addr));
}
__device__ __forceinline__ void mma_f16(float* d,
                                        const uint32_t* a, uint32_t b0, uint32_t b1) {
    asm volatile(
        "mma.sync.aligned.m16n8k16.row.col.f32.f16.f16.f32 "
        "{%0,%1,%2,%3}, {%4,%5,%6,%7}, {%8,%9}, {%0,%1,%2,%3};"
        : "+f"(d[0]), "+f"(d[1]), "+f"(d[2]), "+f"(d[3])
        : "r"(a[0]), "r"(a[1]), "r"(a[2]), "r"(a[3]), "r"(b0), "r"(b1));
}
__device__ __forceinline__ uint32_t h2pack(float a, float b) {
    __half2 h = __floats2half2_rn(a, b);
    return *reinterpret_cast<uint32_t*>(&h);
}
__device__ __forceinline__ uint32_t tile_addr(uint32_t base, int row, int chunk) {
    return base + row * 128 + ((chunk ^ (row & 7)) << 4);
}
__device__ __forceinline__ uint32_t frag_addr(uint32_t base, int base_row, int kt, int lane) {
    int r = base_row + (lane & 15);
    int chunk = kt * 2 + (lane >> 4);
    return tile_addr(base, r, chunk);
}
__device__ __forceinline__ void spin_until(volatile unsigned* p, unsigned target) {
    while (*p < target) __nanosleep(128);
}
__device__ __forceinline__ void release(unsigned* ctr) {
    __threadfence();
    __syncthreads();
    if (threadIdx.x == 0) atomicAdd(ctr, 1u);
}

// ---- f32 -> h convert, 16-deep MLP batches (128 threads, n4 float4s) ----
__device__ __forceinline__ void cvt_chunk(const float* __restrict__ in,
                                          __half* __restrict__ out,
                                          size_t base4, int n4, int tid) {
    // n4 must be a multiple of 128*16
    for (int b = 0; b < n4; b += 128 * 16) {
        float4 v[16];
        #pragma unroll
        for (int t = 0; t < 16; t++)
            v[t] = *reinterpret_cast<const float4*>(in + (base4 + b + t * 128 + tid) * 4);
        #pragma unroll
        for (int t = 0; t < 16; t++) {
            __half2 h0 = __floats2half2_rn(v[t].x, v[t].y);
            __half2 h1 = __floats2half2_rn(v[t].z, v[t].w);
            *reinterpret_cast<uint2*>(out + (base4 + b + t * 128 + tid) * 4) =
                make_uint2(*(uint32_t*)&h0, *(uint32_t*)&h1);
        }
    }
}

// ---------------- GEMM tile: 128 threads, 4 warps of 64x64 -------------------
template <bool IS1>
__device__ __forceinline__ void gemm_tile(
    uint32_t sbase, int tid, int m, int n,
    const __half* __restrict__ A, const __half* __restrict__ B,
    const float* __restrict__ bias, __half* __restrict__ Ts, float* __restrict__ out)
{
    constexpr int K   = IS1 ? 4096 : 1024;
    constexpr int LDA = IS1 ? 4096 : 1024;
    constexpr int LDB = IS1 ? 4096 : 1024;
    constexpr int LDC = IS1 ? 1024 : 4096;
    constexpr int T = K / CTA_K;

    const int lane = tid & 31, wid = tid >> 5;
    const int wm = wid >> 1, wn = wid & 1;        // 2 x 2 warps, warp tile 64x64
    const int lrow = tid >> 3, lc = tid & 7;      // lrow 0..15
    const int bm = m * CTA_M, bn = n * CTA_N;

    auto load_stage = [&](int s, int k0) {
        uint32_t sa = sbase + s * STAGE_BYTES;
        uint32_t sb = sa + A_BYTES;
        const __half* gA = A + (size_t)bm * LDA + k0 + lc * 8;
        const __half* gB = B + (size_t)bn * LDB + k0 + lc * 8;
        #pragma unroll
        for (int j = 0; j < 8; j++) {
            int r = lrow + 16 * j;
            cp16(tile_addr(sa, r, lc), gA + (size_t)r * LDA);
        }
        #pragma unroll
        for (int j = 0; j < 8; j++) {
            int r = lrow + 16 * j;
            cp16(tile_addr(sb, r, lc), gB + (size_t)r * LDB);
        }
    };

    float acc[4][8][4];
    #pragma unroll
    for (int i = 0; i < 4; i++)
        #pragma unroll
        for (int j = 0; j < 8; j++)
            #pragma unroll
            for (int r = 0; r < 4; r++)
                acc[i][j][r] = 0.0f;

    load_stage(0, 0); cp_commit();
    load_stage(1, CTA_K); cp_commit();

    for (int it = 0; it < T; ++it) {
        cp_wait<1>();
        __syncthreads();
        if (it + 2 < T) load_stage((it + 2) % NSTAGES, (it + 2) * CTA_K);
        cp_commit();

        const int s = it % NSTAGES;
        const uint32_t sa = sbase + s * STAGE_BYTES;
        const uint32_t sb = sa + A_BYTES;

        #pragma unroll
        for (int kt = 0; kt < 4; kt++) {
            uint32_t af[4][4];
            #pragma unroll
            for (int mt = 0; mt < 4; mt++)
                ldsm4(af[mt], frag_addr(sa, wm * 64 + mt * 16, kt, lane));
            #pragma unroll
            for (int ng = 0; ng < 4; ng++) {
                uint32_t bf[4];
                ldsm4(bf, frag_addr(sb, wn * 64 + ng * 16, kt, lane));
                #pragma unroll
                for (int mt = 0; mt < 4; mt++) {
                    mma_f16(acc[mt][2 * ng],     af[mt], bf[0], bf[2]);
                    mma_f16(acc[mt][2 * ng + 1], af[mt], bf[1], bf[3]);
                }
            }
        }
    }

    const int g = lane >> 2, tig = lane & 3;
    if (IS1) {
        #pragma unroll
        for (int mt = 0; mt < 4; mt++) {
            #pragma unroll
            for (int nt = 0; nt < 8; nt++) {
                int row = bm + wm * 64 + mt * 16 + g;
                int col = bn + wn * 64 + nt * 8 + tig * 2;
                *reinterpret_cast<uint32_t*>(Ts + (size_t)row * LDC + col) =
                    h2pack(acc[mt][nt][0], acc[mt][nt][1]);
                *reinterpret_cast<uint32_t*>(Ts + (size_t)(row + 8) * LDC + col) =
                    h2pack(acc[mt][nt][2], acc[mt][nt][3]);
            }
        }
        release(&g_mdone[m]);
    } else {
        #pragma unroll
        for (int mt = 0; mt < 4; mt++) {
            #pragma unroll
            for (int nt = 0; nt < 8; nt++) {
                int row = bm + wm * 64 + mt * 16 + g;
                int col = bn + wn * 64 + nt * 8 + tig * 2;
                float2 b = *reinterpret_cast<const float2*>(bias + col);
                *reinterpret_cast<float2*>(out + (size_t)row * LDC + col) =
                    make_float2(acc[mt][nt][0] + b.x, acc[mt][nt][1] + b.y);
                *reinterpret_cast<float2*>(out + (size_t)(row + 8) * LDC + col) =
                    make_float2(acc[mt][nt][2] + b.x, acc[mt][nt][3] + b.y);
            }
        }
    }
}

// ---------------- megakernel: prep + GEMM1 + GEMM2 in one launch -------------
__global__ __launch_bounds__(128, 2) void fused_all(
    const float* __restrict__ x, const float* __restrict__ U,
    const float* __restrict__ V, const float* __restrict__ S,
    const float* __restrict__ bias, float* __restrict__ out)
{
    extern __shared__ char sm[];
    const int tid = threadIdx.x;
    const int bid = blockIdx.x;

    if (bid < PREP_BLKS) {
        // ---- (a) 8 V-transpose tiles: Vth[n][k] = h(V[k][n]*S[n]) ----
        float (*t)[33] = reinterpret_cast<float(*)[33]>(sm);
        const int tx = tid & 31, ty = tid >> 5;   // ty 0..3
        #pragma unroll 1
        for (int f = 0; f < 8; f++) {
            const int vb = bid * 8 + f;           // 4096 fine tiles
            const int k0 = (vb & 127) * 32;
            const int n0 = (vb >> 7) * 32;
            #pragma unroll
            for (int r = ty; r < 32; r += 4)
                t[r][tx] = V[(size_t)(k0 + r) * 1024 + n0 + tx];
            __syncthreads();
            #pragma unroll
            for (int r = ty; r < 32; r += 4)
                g_Vth[(size_t)(n0 + r) * 4096 + k0 + tx] =
                    __float2half_rn(t[tx][r] * S[n0 + r]);
            __syncthreads();
        }
        release(&g_vdone);

        // ---- (b) x chunk: rows [16*bid, 16*bid+16) -> fp16 ----
        // 16 rows x 4096 = 65536 f32 = 16384 float4
        cvt_chunk(x, g_xh, (size_t)bid * 16384, 16384, tid);
        release(&g_xdone[bid >> 3]);

        // ---- (c) U chunk: 1/512 of 4096x1024 -> fp16 (2048 float4) ----
        cvt_chunk(U, g_Uh, (size_t)bid * 2048, 2048, tid);
        release(&g_udone);
        return;
    }

    const uint32_t sbase = smem_u32(sm);
    if (bid < PREP_BLKS + G1_TILES) {
        const int t1 = bid - PREP_BLKS;
        const int m = t1 >> 3, n = t1 & 7;
        if (tid == 0) {
            spin_until(&g_vdone, PREP_BLKS);
            spin_until(&g_xdone[m], 8u);
        }
        __syncthreads();
        __threadfence();
        gemm_tile<true>(sbase, tid, m, n, g_xh, g_Vth, bias, g_Ts, out);
    } else {
        const int t2 = bid - PREP_BLKS - G1_TILES;
        const int m = t2 >> 5, n = t2 & 31;
        if (tid == 0) {
            spin_until(&g_udone, PREP_BLKS);
            spin_until(&g_mdone[m], 8u);
        }
        __syncthreads();
        __threadfence();
        gemm_tile<false>(sbase, tid, m, n, g_Ts, g_Uh, bias, g_Ts, out);
    }
}

extern "C" void kernel_launch(void* const* d_in, const int* in_sizes, int n_in,
                              void* d_out, int out_size)
{
    const float* x    = (const float*)d_in[0];   // [8192,4096]
    const float* U    = (const float*)d_in[1];   // [4096,1024]
    const float* S    = (const float*)d_in[2];   // [1024]
    const float* V    = (const float*)d_in[3];   // [4096,1024]
    const float* bias = (const float*)d_in[4];   // [4096]
    float* out = (float*)d_out;                  // [8192,4096]

    void *vd, *ud, *xd, *md;
    cudaGetSymbolAddress(&vd, g_vdone);
    cudaGetSymbolAddress(&ud, g_udone);
    cudaGetSymbolAddress(&xd, g_xdone);
    cudaGetSymbolAddress(&md, g_mdone);
    cudaMemsetAsync(vd, 0, sizeof(unsigned));
    cudaMemsetAsync(ud, 0, sizeof(unsigned));
    cudaMemsetAsync(xd, 0, 64 * sizeof(unsigned));
    cudaMemsetAsync(md, 0, 64 * sizeof(unsigned));

    cudaFuncSetAttribute(fused_all,
                         cudaFuncAttributeMaxDynamicSharedMemorySize, SMEM_TOTAL);

    fused_all<<<N_BLOCKS, 128, SMEM_TOTAL>>>(x, U, V, S, bias, out);
}